// round 1
// baseline (speedup 1.0000x reference)
#include <cuda_runtime.h>
#include <math.h>

#define N_NODES 50000
#define N_EDGES 800000
#define NUM_RELS 16
#define H_DIM 128
#define LIN_DIM 512

// generous caps (expected: |S1|~16, |S2|~256, |E1|~16, |E2|~256)
#define CAP1 512
#define CAP2 4096
#define CAPE1 2048
#define CAPE2 16384

// ---------------- scratch (device globals; no allocation) ----------------
__device__ int   g_slot1[N_NODES];        // node -> slot in S1 (-1 = absent)
__device__ int   g_slot2[N_NODES];        // node -> slot in S2
__device__ int   g_n1, g_n2, g_ne1, g_ne2;
__device__ int   g_s1_nodes[CAP1];
__device__ int   g_s2_nodes[CAP2];
__device__ int   g_e1_src[CAPE1];         // srcs of edges with dst == 0
__device__ int   g_e2_src[CAPE2];         // srcs of edges with dst in S1
__device__ int   g_e2_dslot[CAPE2];       // slot1 of dst for those edges
__device__ float g_T0[NUM_RELS * H_DIM];  // T0[r][j] = W0[r][r][j]
__device__ float g_h1acc[CAP2 * H_DIM];   // pre-relu h1 for S2 nodes
__device__ float g_h2acc[CAP1 * H_DIM];   // pre-relu h2 for S1 nodes
__device__ float g_msg1[CAP2 * H_DIM];
__device__ float g_msg2[CAP1 * H_DIM];

// ---------------- kernels ----------------

__global__ void k_clear(const float* __restrict__ W0) {
    const int total = CAP2 * H_DIM;  // largest array to clear (524288)
    for (int i = blockIdx.x * blockDim.x + threadIdx.x; i < total;
         i += gridDim.x * blockDim.x) {
        g_h1acc[i] = 0.f;
        if (i < CAP1 * H_DIM) g_h2acc[i] = 0.f;
        if (i < N_NODES) { g_slot1[i] = -1; g_slot2[i] = -1; }
        if (i < NUM_RELS * H_DIM) {
            int r = i >> 7, j = i & 127;
            g_T0[i] = W0[(r * NUM_RELS + r) * H_DIM + j];  // one-hot @ W0[r]
        }
        if (i == 0) { g_n1 = 0; g_n2 = 0; g_ne1 = 0; g_ne2 = 0; }
    }
}

// Pass 1: edges with dst == 0 -> E1 list, register srcs into S1
__global__ void k_scan1(const int* __restrict__ src, const int* __restrict__ dst) {
    int i0 = (blockIdx.x * blockDim.x + threadIdx.x) * 4;
    if (i0 >= N_EDGES) return;
    const int4 d4 = *reinterpret_cast<const int4*>(dst + i0);
    int dv[4] = {d4.x, d4.y, d4.z, d4.w};
#pragma unroll
    for (int k = 0; k < 4; k++) {
        if (dv[k] == 0) {
            int s = src[i0 + k];
            int p = atomicAdd(&g_ne1, 1);
            if (p < CAPE1) g_e1_src[p] = s;
            if (atomicCAS(&g_slot1[s], -1, -2) == -1) {
                int sl = atomicAdd(&g_n1, 1);
                if (sl < CAP1) g_s1_nodes[sl] = s;
                g_slot1[s] = sl;
            }
        }
    }
}

// Pass 2: edges with dst in S1 -> E2 list, register srcs into S2
__global__ void k_scan2(const int* __restrict__ src, const int* __restrict__ dst) {
    int i0 = (blockIdx.x * blockDim.x + threadIdx.x) * 4;
    if (i0 >= N_EDGES) return;
    const int4 d4 = *reinterpret_cast<const int4*>(dst + i0);
    int dv[4] = {d4.x, d4.y, d4.z, d4.w};
#pragma unroll
    for (int k = 0; k < 4; k++) {
        int sl = g_slot1[dv[k]];
        if (sl >= 0) {
            int s = src[i0 + k];
            int p = atomicAdd(&g_ne2, 1);
            if (p < CAPE2) { g_e2_src[p] = s; g_e2_dslot[p] = sl; }
            if (atomicCAS(&g_slot2[s], -1, -2) == -1) {
                int q = atomicAdd(&g_n2, 1);
                if (q < CAP2) g_s2_nodes[q] = s;
                g_slot2[s] = q;
            }
        }
    }
}

// Pass 3: edges with dst in S2 -> accumulate layer-0 messages directly:
// h1acc[slot2[dst]] += T0[cls[src]] * norm[src]
__global__ void k_scan3(const int* __restrict__ src, const int* __restrict__ dst,
                        const int* __restrict__ cls, const float* __restrict__ norm) {
    int i0 = (blockIdx.x * blockDim.x + threadIdx.x) * 4;
    if (i0 >= N_EDGES) return;
    const int4 d4 = *reinterpret_cast<const int4*>(dst + i0);
    int dv[4] = {d4.x, d4.y, d4.z, d4.w};
#pragma unroll
    for (int k = 0; k < 4; k++) {
        int sl = g_slot2[dv[k]];
        if (sl >= 0 && sl < CAP2) {
            int s = src[i0 + k];
            int c = cls[s];
            float nm = norm[s];
            const float* t0 = &g_T0[c * H_DIM];
            float* acc = &g_h1acc[sl * H_DIM];
#pragma unroll 4
            for (int j = 0; j < H_DIM; j++) atomicAdd(acc + j, t0[j] * nm);
        }
    }
}

// Per-frontier-node: h = relu(acc); msg = (h @ W[cls[node]]) * norm[node]
// layer==1: S2/W1 -> msg1 ; layer==2: S1/W2 -> msg2
__global__ void k_node_msg(int layer, const float* __restrict__ W,
                           const int* __restrict__ cls,
                           const float* __restrict__ norm) {
    int sl = blockIdx.x;
    int n  = (layer == 1) ? min(g_n2, CAP2) : min(g_n1, CAP1);
    if (sl >= n) return;
    int node = (layer == 1) ? g_s2_nodes[sl] : g_s1_nodes[sl];
    const float* accp = (layer == 1) ? &g_h1acc[sl * H_DIM] : &g_h2acc[sl * H_DIM];
    float* outp       = (layer == 1) ? &g_msg1[sl * H_DIM]  : &g_msg2[sl * H_DIM];

    __shared__ float h[H_DIM];
    int j = threadIdx.x;
    h[j] = fmaxf(accp[j], 0.f);
    __syncthreads();

    int c = cls[node];
    float nm = norm[node];
    const float* Wc = W + c * H_DIM * H_DIM;
    float a = 0.f;
#pragma unroll 8
    for (int k = 0; k < H_DIM; k++) a = fmaf(h[k], Wc[k * H_DIM + j], a);
    outp[j] = a * nm;
}

// Aggregate layer-2: for each E2 edge, h2acc[dslot] += msg1[slot2[src]]
__global__ void k_agg2() {
    int warps_per_blk = blockDim.x >> 5;
    int idx  = blockIdx.x * warps_per_blk + (threadIdx.x >> 5);
    int lane = threadIdx.x & 31;
    int ne = min(g_ne2, CAPE2);
    if (idx >= ne) return;
    int s   = g_e2_src[idx];
    int dsl = g_e2_dslot[idx];
    int ssl = g_slot2[s];
    if (ssl < 0 || ssl >= CAP2 || dsl >= CAP1) return;
    const float* m = &g_msg1[ssl * H_DIM];
    float* a = &g_h2acc[dsl * H_DIM];
#pragma unroll
    for (int j = lane; j < H_DIM; j += 32) atomicAdd(a + j, m[j]);
}

// Final: aggregate node-0 layer-3 pre-activation, softmax, actor + critic heads
__global__ void k_final(const float* __restrict__ a1_w, const float* __restrict__ a1_b,
                        const float* __restrict__ a2_w, const float* __restrict__ a2_b,
                        const float* __restrict__ c1_w, const float* __restrict__ c1_b,
                        const float* __restrict__ c2_w, const float* __restrict__ c2_b,
                        float* __restrict__ out, int out_size) {
    __shared__ float red[H_DIM];
    __shared__ float root[H_DIM];
    __shared__ float hid[LIN_DIM];
    __shared__ float s_mx, s_sum;
    int t = threadIdx.x;

    // sum msg2 over edges into node 0
    if (t < H_DIM) {
        float a = 0.f;
        int ne = min(g_ne1, CAPE1);
        for (int i = 0; i < ne; i++) {
            int s  = g_e1_src[i];
            int sl = g_slot1[s];
            if (sl >= 0 && sl < CAP1) a += g_msg2[sl * H_DIM + t];
        }
        red[t] = a;
    }
    __syncthreads();

    // softmax over 128 (serial reductions; tiny)
    if (t == 0) {
        float mx = -1e30f;
        for (int i = 0; i < H_DIM; i++) mx = fmaxf(mx, red[i]);
        s_mx = mx;
    }
    __syncthreads();
    if (t < H_DIM) red[t] = expf(red[t] - s_mx);
    __syncthreads();
    if (t == 0) {
        float sm = 0.f;
        for (int i = 0; i < H_DIM; i++) sm += red[i];
        s_sum = sm;
    }
    __syncthreads();
    if (t < H_DIM) root[t] = red[t] / s_sum;
    __syncthreads();

    // actor head: 128 -> 512 (relu) -> 128
    {
        float a = a1_b[t];
#pragma unroll 8
        for (int k = 0; k < H_DIM; k++) a = fmaf(root[k], a1_w[k * LIN_DIM + t], a);
        hid[t] = fmaxf(a, 0.f);
    }
    __syncthreads();
    if (t < H_DIM) {
        float a = a2_b[t];
#pragma unroll 8
        for (int k = 0; k < LIN_DIM; k++) a = fmaf(hid[k], a2_w[k * H_DIM + t], a);
        out[t] = a;
    }
    __syncthreads();

    // critic head: 128 -> 512 (relu) -> 1
    {
        float a = c1_b[t];
#pragma unroll 8
        for (int k = 0; k < H_DIM; k++) a = fmaf(root[k], c1_w[k * LIN_DIM + t], a);
        hid[t] = fmaxf(a, 0.f);
    }
    __syncthreads();
    if (t == 0) {
        float a = c2_b[0];
        for (int k = 0; k < LIN_DIM; k++) a = fmaf(hid[k], c2_w[k], a);
        if (out_size > H_DIM) out[H_DIM] = a;
    }
}

// ---------------- launch ----------------
extern "C" void kernel_launch(void* const* d_in, const int* in_sizes, int n_in,
                              void* d_out, int out_size) {
    const int*   cls  = (const int*)  d_in[0];   // op_class_id
    const float* norm = (const float*)d_in[1];
    const int*   src  = (const int*)  d_in[2];
    const int*   dst  = (const int*)  d_in[3];
    const float* W0   = (const float*)d_in[4];
    const float* W1   = (const float*)d_in[5];
    const float* W2   = (const float*)d_in[6];
    const float* a1_w = (const float*)d_in[7];
    const float* a1_b = (const float*)d_in[8];
    const float* a2_w = (const float*)d_in[9];
    const float* a2_b = (const float*)d_in[10];
    const float* c1_w = (const float*)d_in[11];
    const float* c1_b = (const float*)d_in[12];
    const float* c2_w = (const float*)d_in[13];
    const float* c2_b = (const float*)d_in[14];
    float* out = (float*)d_out;

    k_clear<<<512, 256>>>(W0);

    int scanBlocks = (N_EDGES / 4 + 255) / 256;
    k_scan1<<<scanBlocks, 256>>>(src, dst);
    k_scan2<<<scanBlocks, 256>>>(src, dst);
    k_scan3<<<scanBlocks, 256>>>(src, dst, cls, norm);

    k_node_msg<<<CAP2, H_DIM>>>(1, W1, cls, norm);
    k_agg2<<<CAPE2 / 8, 256>>>();
    k_node_msg<<<CAP1, H_DIM>>>(2, W2, cls, norm);

    k_final<<<1, LIN_DIM>>>(a1_w, a1_b, a2_w, a2_b, c1_w, c1_b, c2_w, c2_b,
                            out, out_size);
}

// round 2
// speedup vs baseline: 1.2737x; 1.2737x over previous
#include <cuda_runtime.h>
#include <math.h>

#define N_NODES 50000
#define N_EDGES 800000
#define NUM_RELS 16
#define H_DIM 128
#define LIN_DIM 512

// caps (expected: |S1|~16, |S2|~300, |E1|~16, |E2|~300; Poisson(16) tails well covered)
#define CAP1 256
#define CAP2 2048
#define CAPE1 512
#define CAPE2 4096

#define BM_WORDS ((N_NODES + 31) / 32)   // 1563

// ---------------- scratch (device globals; no allocation) ----------------
__device__ int          g_slot1[N_NODES];
__device__ int          g_slot2[N_NODES];
__device__ unsigned int g_bm1[BM_WORDS + 1];   // S1 membership bitmap (L1-resident)
__device__ unsigned int g_bm2[BM_WORDS + 1];   // S2 membership bitmap
__device__ int   g_n1, g_n2, g_ne1, g_ne2;
__device__ int   g_s1_nodes[CAP1];
__device__ int   g_s2_nodes[CAP2];
__device__ int   g_e1_src[CAPE1];
__device__ int   g_e2_src[CAPE2];
__device__ int   g_e2_dslot[CAPE2];
__device__ float g_T0[NUM_RELS * H_DIM];       // T0[r][j] = W0[r][r][j]
__device__ float g_h1acc[CAP2 * H_DIM];
__device__ float g_h2acc[CAP1 * H_DIM];
__device__ float g_msg1[CAP2 * H_DIM];
__device__ float g_msg2[CAP1 * H_DIM];

// ---------------- kernels ----------------

__global__ void k_clear(const float* __restrict__ W0) {
    // float4-vectorized clears. Largest region: h1acc = CAP2*H_DIM = 262144 floats
    const int nv = (CAP2 * H_DIM) / 4;  // 65536 float4
    float4 z = make_float4(0.f, 0.f, 0.f, 0.f);
    for (int i = blockIdx.x * blockDim.x + threadIdx.x; i < nv;
         i += gridDim.x * blockDim.x) {
        reinterpret_cast<float4*>(g_h1acc)[i] = z;
        if (i < (CAP1 * H_DIM) / 4) reinterpret_cast<float4*>(g_h2acc)[i] = z;
        if (i < (N_NODES + 3) / 4) {
            int4 m1 = make_int4(-1, -1, -1, -1);
            reinterpret_cast<int4*>(g_slot1)[i] = m1;
            reinterpret_cast<int4*>(g_slot2)[i] = m1;
        }
        if (i <= BM_WORDS) { g_bm1[i] = 0u; g_bm2[i] = 0u; }
        if (i < NUM_RELS * H_DIM) {
            int r = i >> 7, j = i & 127;
            g_T0[i] = W0[(r * NUM_RELS + r) * H_DIM + j];
        }
        if (i == 0) { g_n1 = 0; g_n2 = 0; g_ne1 = 0; g_ne2 = 0; }
    }
}

// Pass 1: edges with dst == 0 -> E1 list, register srcs into S1 (+bm1)
__global__ void __launch_bounds__(256) k_scan1(const int* __restrict__ src,
                                               const int* __restrict__ dst) {
    int i0 = (blockIdx.x * blockDim.x + threadIdx.x) * 4;
    if (i0 >= N_EDGES) return;
    const int4 d4 = *reinterpret_cast<const int4*>(dst + i0);
    int dv[4] = {d4.x, d4.y, d4.z, d4.w};
#pragma unroll
    for (int k = 0; k < 4; k++) {
        if (dv[k] == 0) {
            int s = src[i0 + k];
            int p = atomicAdd(&g_ne1, 1);
            if (p < CAPE1) g_e1_src[p] = s;
            if (atomicCAS(&g_slot1[s], -1, -2) == -1) {
                int sl = atomicAdd(&g_n1, 1);
                if (sl < CAP1) g_s1_nodes[sl] = s;
                g_slot1[s] = sl;
                atomicOr(&g_bm1[s >> 5], 1u << (s & 31));
            }
        }
    }
}

// Pass 2: edges with dst in S1 (bitmap fast-path) -> E2 list, register srcs into S2 (+bm2)
__global__ void __launch_bounds__(256) k_scan2(const int* __restrict__ src,
                                               const int* __restrict__ dst) {
    int i0 = (blockIdx.x * blockDim.x + threadIdx.x) * 4;
    if (i0 >= N_EDGES) return;
    const int4 d4 = *reinterpret_cast<const int4*>(dst + i0);
    int dv[4] = {d4.x, d4.y, d4.z, d4.w};
#pragma unroll
    for (int k = 0; k < 4; k++) {
        int d = dv[k];
        // L1-resident bitmap test (6.25KB table) instead of 200KB slot-table L2 hit
        if (g_bm1[d >> 5] & (1u << (d & 31))) {
            int sl = g_slot1[d];
            if (sl >= 0 && sl < CAP1) {
                int s = src[i0 + k];
                int p = atomicAdd(&g_ne2, 1);
                if (p < CAPE2) { g_e2_src[p] = s; g_e2_dslot[p] = sl; }
                if (atomicCAS(&g_slot2[s], -1, -2) == -1) {
                    int q = atomicAdd(&g_n2, 1);
                    if (q < CAP2) g_s2_nodes[q] = s;
                    g_slot2[s] = q;
                    atomicOr(&g_bm2[s >> 5], 1u << (s & 31));
                }
            }
        }
    }
}

// Pass 3: edges with dst in S2 (bitmap fast-path) -> accumulate layer-0 messages:
// h1acc[slot2[dst]] += T0[cls[src]] * norm[src]    (warp-cooperative on hits)
__global__ void __launch_bounds__(256) k_scan3(const int* __restrict__ src,
                                               const int* __restrict__ dst,
                                               const int* __restrict__ cls,
                                               const float* __restrict__ norm) {
    int tid  = blockIdx.x * blockDim.x + threadIdx.x;
    int lane = threadIdx.x & 31;
    int i0 = tid * 4;
    int dv[4] = {-1, -1, -1, -1};
    if (i0 < N_EDGES) {
        const int4 d4 = *reinterpret_cast<const int4*>(dst + i0);
        dv[0] = d4.x; dv[1] = d4.y; dv[2] = d4.z; dv[3] = d4.w;
    }
#pragma unroll
    for (int k = 0; k < 4; k++) {
        int d = dv[k];
        bool hit = (d >= 0) && (g_bm2[d >> 5] & (1u << (d & 31)));
        unsigned mask = __ballot_sync(0xffffffffu, hit);
        if (mask == 0) continue;
        // this thread's payload (valid only if hit)
        int my_sl = -1, my_s = 0;
        if (hit) { my_sl = g_slot2[d]; my_s = src[i0 + k]; }
        // warp cooperates on each hit lane: 32 lanes x 4 atomics = 128
        while (mask) {
            int h = __ffs(mask) - 1;
            mask &= mask - 1;
            int sl = __shfl_sync(0xffffffffu, my_sl, h);
            int s  = __shfl_sync(0xffffffffu, my_s, h);
            if (sl < 0 || sl >= CAP2) continue;
            int c = cls[s];
            float nm = norm[s];
            const float* t0 = &g_T0[c * H_DIM];
            float* acc = &g_h1acc[sl * H_DIM];
#pragma unroll
            for (int j = 0; j < 4; j++) {
                int col = lane + j * 32;
                atomicAdd(acc + col, t0[col] * nm);
            }
        }
    }
}

// Per-frontier-node: h = relu(acc); msg = (h @ W[cls[node]]) * norm[node]
__global__ void __launch_bounds__(128) k_node_msg(int layer, const float* __restrict__ W,
                                                  const int* __restrict__ cls,
                                                  const float* __restrict__ norm) {
    int sl = blockIdx.x;
    int n  = (layer == 1) ? min(g_n2, CAP2) : min(g_n1, CAP1);
    if (sl >= n) return;
    int node = (layer == 1) ? g_s2_nodes[sl] : g_s1_nodes[sl];
    const float* accp = (layer == 1) ? &g_h1acc[sl * H_DIM] : &g_h2acc[sl * H_DIM];
    float* outp       = (layer == 1) ? &g_msg1[sl * H_DIM]  : &g_msg2[sl * H_DIM];

    __shared__ float h[H_DIM];
    int j = threadIdx.x;
    h[j] = fmaxf(accp[j], 0.f);
    __syncthreads();

    int c = cls[node];
    float nm = norm[node];
    const float* Wc = W + c * H_DIM * H_DIM;
    float a = 0.f;
#pragma unroll 8
    for (int k = 0; k < H_DIM; k++) a = fmaf(h[k], Wc[k * H_DIM + j], a);
    outp[j] = a * nm;
}

// Aggregate layer-2: for each E2 edge, h2acc[dslot] += msg1[slot2[src]]
__global__ void __launch_bounds__(256) k_agg2() {
    int warps_per_blk = blockDim.x >> 5;
    int idx  = blockIdx.x * warps_per_blk + (threadIdx.x >> 5);
    int lane = threadIdx.x & 31;
    int ne = min(g_ne2, CAPE2);
    if (idx >= ne) return;
    int s   = g_e2_src[idx];
    int dsl = g_e2_dslot[idx];
    int ssl = g_slot2[s];
    if (ssl < 0 || ssl >= CAP2 || dsl >= CAP1) return;
    const float* m = &g_msg1[ssl * H_DIM];
    float* a = &g_h2acc[dsl * H_DIM];
#pragma unroll
    for (int j = lane; j < H_DIM; j += 32) atomicAdd(a + j, m[j]);
}

// Final: node-0 layer-3 aggregate, softmax, actor + critic heads
__global__ void __launch_bounds__(512) k_final(
        const float* __restrict__ a1_w, const float* __restrict__ a1_b,
        const float* __restrict__ a2_w, const float* __restrict__ a2_b,
        const float* __restrict__ c1_w, const float* __restrict__ c1_b,
        const float* __restrict__ c2_w, const float* __restrict__ c2_b,
        float* __restrict__ out, int out_size) {
    __shared__ float red[H_DIM];
    __shared__ float root[H_DIM];
    __shared__ float hid[LIN_DIM];
    __shared__ float s_mx, s_sum;
    int t = threadIdx.x;

    if (t < H_DIM) {
        float a = 0.f;
        int ne = min(g_ne1, CAPE1);
        for (int i = 0; i < ne; i++) {
            int s  = g_e1_src[i];
            int sl = g_slot1[s];
            if (sl >= 0 && sl < CAP1) a += g_msg2[sl * H_DIM + t];
        }
        red[t] = a;
    }
    __syncthreads();

    if (t == 0) {
        float mx = -1e30f;
        for (int i = 0; i < H_DIM; i++) mx = fmaxf(mx, red[i]);
        s_mx = mx;
    }
    __syncthreads();
    if (t < H_DIM) red[t] = expf(red[t] - s_mx);
    __syncthreads();
    if (t == 0) {
        float sm = 0.f;
        for (int i = 0; i < H_DIM; i++) sm += red[i];
        s_sum = sm;
    }
    __syncthreads();
    if (t < H_DIM) root[t] = red[t] / s_sum;
    __syncthreads();

    // actor: 128 -> 512 relu -> 128
    {
        float a = a1_b[t];
#pragma unroll 8
        for (int k = 0; k < H_DIM; k++) a = fmaf(root[k], a1_w[k * LIN_DIM + t], a);
        hid[t] = fmaxf(a, 0.f);
    }
    __syncthreads();
    if (t < H_DIM) {
        float a = a2_b[t];
#pragma unroll 8
        for (int k = 0; k < LIN_DIM; k++) a = fmaf(hid[k], a2_w[k * H_DIM + t], a);
        out[t] = a;
    }
    __syncthreads();

    // critic: 128 -> 512 relu -> 1
    {
        float a = c1_b[t];
#pragma unroll 8
        for (int k = 0; k < H_DIM; k++) a = fmaf(root[k], c1_w[k * LIN_DIM + t], a);
        hid[t] = fmaxf(a, 0.f);
    }
    __syncthreads();
    if (t == 0) {
        float a = c2_b[0];
        for (int k = 0; k < LIN_DIM; k++) a = fmaf(hid[k], c2_w[k], a);
        if (out_size > H_DIM) out[H_DIM] = a;
    }
}

// ---------------- launch ----------------
extern "C" void kernel_launch(void* const* d_in, const int* in_sizes, int n_in,
                              void* d_out, int out_size) {
    const int*   cls  = (const int*)  d_in[0];
    const float* norm = (const float*)d_in[1];
    const int*   src  = (const int*)  d_in[2];
    const int*   dst  = (const int*)  d_in[3];
    const float* W0   = (const float*)d_in[4];
    const float* W1   = (const float*)d_in[5];
    const float* W2   = (const float*)d_in[6];
    const float* a1_w = (const float*)d_in[7];
    const float* a1_b = (const float*)d_in[8];
    const float* a2_w = (const float*)d_in[9];
    const float* a2_b = (const float*)d_in[10];
    const float* c1_w = (const float*)d_in[11];
    const float* c1_b = (const float*)d_in[12];
    const float* c2_w = (const float*)d_in[13];
    const float* c2_b = (const float*)d_in[14];
    float* out = (float*)d_out;

    k_clear<<<256, 256>>>(W0);

    int scanBlocks = (N_EDGES / 4 + 255) / 256;  // 782
    k_scan1<<<scanBlocks, 256>>>(src, dst);
    k_scan2<<<scanBlocks, 256>>>(src, dst);
    k_scan3<<<scanBlocks, 256>>>(src, dst, cls, norm);

    k_node_msg<<<CAP2, H_DIM>>>(1, W1, cls, norm);
    k_agg2<<<CAPE2 / 8, 256>>>();
    k_node_msg<<<CAP1, H_DIM>>>(2, W2, cls, norm);

    k_final<<<1, LIN_DIM>>>(a1_w, a1_b, a2_w, a2_b, c1_w, c1_b, c2_w, c2_b,
                            out, out_size);
}